// round 7
// baseline (speedup 1.0000x reference)
#include <cuda_runtime.h>
#include <math.h>

// Problem constants (fixed by the reference)
#define T_TOK 8192
#define H_DIM 2048
#define F_DIM 1408
#define E_NUM 8
#define F2    (2 * F_DIM)

// ---------------------------------------------------------------------------
// Static device scratch (no allocation allowed anywhere)
// ---------------------------------------------------------------------------
__device__ int   g_cnt[E_NUM];                                   // tokens per expert
__device__ int   g_tok[E_NUM * T_TOK];                           // token id per slot
__device__ float g_wgt[E_NUM * T_TOK];                           // routing weight per slot
__device__ float g_act[(long long)E_NUM * T_TOK * F_DIM];        // silu(gate)*up per slot

// ---------------------------------------------------------------------------
// Kernel 0: zero the output and the expert counters (runs every replay)
// ---------------------------------------------------------------------------
__global__ void init_kernel(float* __restrict__ out) {
    int idx = blockIdx.x * blockDim.x + threadIdx.x;
    if (idx < E_NUM) g_cnt[idx] = 0;
    const long long n = (long long)T_TOK * H_DIM;
    long long stride = (long long)gridDim.x * blockDim.x;
    for (long long i = idx; i < n; i += stride) out[i] = 0.0f;
}

// ---------------------------------------------------------------------------
// Kernel 1: softmax + top-2 routing, gather tokens per expert
// ---------------------------------------------------------------------------
__global__ void route_kernel(const float* __restrict__ logits) {
    int t = blockIdx.x * blockDim.x + threadIdx.x;
    if (t >= T_TOK) return;

    float l[E_NUM];
#pragma unroll
    for (int i = 0; i < E_NUM; i++) l[i] = logits[t * E_NUM + i];

    // top-1 (ties -> lower index, strict > keeps earliest)
    int   i0 = 0;
    float v0 = l[0];
#pragma unroll
    for (int i = 1; i < E_NUM; i++) {
        if (l[i] > v0) { v0 = l[i]; i0 = i; }
    }
    // top-2
    int   i1 = -1;
    float v1 = -3.402823466e+38f;
#pragma unroll
    for (int i = 0; i < E_NUM; i++) {
        if (i != i0 && l[i] > v1) { v1 = l[i]; i1 = i; }
    }

    // normalized top-2 softmax weights: w0 = e^{v0} / (e^{v0} + e^{v1})
    float r  = expf(v1 - v0);          // <= 1, stable
    float w0 = 1.0f / (1.0f + r);
    float w1 = r / (1.0f + r);

    int p0 = atomicAdd(&g_cnt[i0], 1);
    g_tok[i0 * T_TOK + p0] = t;
    g_wgt[i0 * T_TOK + p0] = w0;

    int p1 = atomicAdd(&g_cnt[i1], 1);
    g_tok[i1 * T_TOK + p1] = t;
    g_wgt[i1 * T_TOK + p1] = w1;
}

// ---------------------------------------------------------------------------
// Kernel 2: GEMM1 (gathered A) + fused SiLU*up
//   Per block: 128 token-slots x (64 gate cols + 64 up cols), K = H_DIM.
//   grid = (T/128, F/64, E); early-exit on empty M tiles.
// ---------------------------------------------------------------------------
__global__ __launch_bounds__(256, 2)
void gemm1_kernel(const float* __restrict__ hidden, const float* __restrict__ w1) {
    const int e   = blockIdx.z;
    const int cnt = g_cnt[e];
    const int m0  = blockIdx.x * 128;
    if (m0 >= cnt) return;
    const int n0  = blockIdx.y * 64;

    __shared__ float As[16 * 132];   // [k][row], padded
    __shared__ float Bg[16 * 68];    // [k][n], gate rows
    __shared__ float Bu[16 * 68];    // [k][n], up rows
    __shared__ int   stok[128];

    const int tid = threadIdx.x;
    const int tx  = tid & 15;        // 0..15  -> 4 cols each (gate & up)
    const int ty  = tid >> 4;        // 0..15  -> 8 rows each

    if (tid < 128) {
        int i = m0 + tid;
        stok[tid] = (i < cnt) ? g_tok[e * T_TOK + i] : 0;
    }
    __syncthreads();

    float accg[8][4];
    float accu[8][4];
#pragma unroll
    for (int i = 0; i < 8; i++)
#pragma unroll
        for (int j = 0; j < 4; j++) { accg[i][j] = 0.0f; accu[i][j] = 0.0f; }

    const float* w1g = w1 + (size_t)e * F2 * H_DIM + (size_t)n0 * H_DIM;
    const float* w1u = w1g + (size_t)F_DIM * H_DIM;

    const int lr  = tid >> 2;          // 0..63
    const int lk4 = (tid & 3) * 4;     // 0,4,8,12

    for (int k0 = 0; k0 < H_DIM; k0 += 16) {
        // ---- A tile: 128 rows x 16 k (gathered) ----
#pragma unroll
        for (int r = 0; r < 2; r++) {
            int row = lr + r * 64;
            float4 v = *(const float4*)(hidden + (size_t)stok[row] * H_DIM + k0 + lk4);
            As[(lk4 + 0) * 132 + row] = v.x;
            As[(lk4 + 1) * 132 + row] = v.y;
            As[(lk4 + 2) * 132 + row] = v.z;
            As[(lk4 + 3) * 132 + row] = v.w;
        }
        // ---- B tiles: 64 rows x 16 k, gate and up ----
        {
            float4 vg = *(const float4*)(w1g + (size_t)lr * H_DIM + k0 + lk4);
            float4 vu = *(const float4*)(w1u + (size_t)lr * H_DIM + k0 + lk4);
            Bg[(lk4 + 0) * 68 + lr] = vg.x;
            Bg[(lk4 + 1) * 68 + lr] = vg.y;
            Bg[(lk4 + 2) * 68 + lr] = vg.z;
            Bg[(lk4 + 3) * 68 + lr] = vg.w;
            Bu[(lk4 + 0) * 68 + lr] = vu.x;
            Bu[(lk4 + 1) * 68 + lr] = vu.y;
            Bu[(lk4 + 2) * 68 + lr] = vu.z;
            Bu[(lk4 + 3) * 68 + lr] = vu.w;
        }
        __syncthreads();

#pragma unroll
        for (int kk = 0; kk < 16; kk++) {
            float4 a0 = *(const float4*)&As[kk * 132 + ty * 8];
            float4 a1 = *(const float4*)&As[kk * 132 + ty * 8 + 4];
            float4 bg = *(const float4*)&Bg[kk * 68 + tx * 4];
            float4 bu = *(const float4*)&Bu[kk * 68 + tx * 4];
            float a[8]  = {a0.x, a0.y, a0.z, a0.w, a1.x, a1.y, a1.z, a1.w};
            float bgv[4] = {bg.x, bg.y, bg.z, bg.w};
            float buv[4] = {bu.x, bu.y, bu.z, bu.w};
#pragma unroll
            for (int i = 0; i < 8; i++)
#pragma unroll
                for (int j = 0; j < 4; j++) {
                    accg[i][j] += a[i] * bgv[j];
                    accu[i][j] += a[i] * buv[j];
                }
        }
        __syncthreads();
    }

    // epilogue: h = silu(gate) * up  -> g_act[slot][n]
    const int slot0 = e * T_TOK + m0;
#pragma unroll
    for (int i = 0; i < 8; i++) {
        int row = ty * 8 + i;
        if (m0 + row < cnt) {
            float4 o;
            float g, u;
            g = accg[i][0]; u = accu[i][0]; o.x = (g / (1.0f + expf(-g))) * u;
            g = accg[i][1]; u = accu[i][1]; o.y = (g / (1.0f + expf(-g))) * u;
            g = accg[i][2]; u = accu[i][2]; o.z = (g / (1.0f + expf(-g))) * u;
            g = accg[i][3]; u = accu[i][3]; o.w = (g / (1.0f + expf(-g))) * u;
            *(float4*)(g_act + (size_t)(slot0 + row) * F_DIM + n0 + tx * 4) = o;
        }
    }
}

// ---------------------------------------------------------------------------
// Kernel 3: GEMM2 (y = act @ w2[e].T) + weighted scatter into out
//   Per block: 128 slots x 128 H-cols, K = F_DIM.
//   grid = (T/128, H/128, E); early-exit on empty M tiles.
// ---------------------------------------------------------------------------
__global__ __launch_bounds__(256, 2)
void gemm2_kernel(const float* __restrict__ w2, float* __restrict__ out) {
    const int e   = blockIdx.z;
    const int cnt = g_cnt[e];
    const int m0  = blockIdx.x * 128;
    if (m0 >= cnt) return;
    const int n0  = blockIdx.y * 128;

    __shared__ float As[16 * 132];
    __shared__ float Bs[16 * 132];
    __shared__ int   stok[128];

    const int tid = threadIdx.x;
    const int tx  = tid & 15;        // 8 cols each
    const int ty  = tid >> 4;        // 8 rows each

    if (tid < 128) {
        int i = m0 + tid;
        stok[tid] = (i < cnt) ? g_tok[e * T_TOK + i] : 0;
    }
    __syncthreads();

    float acc[8][8];
#pragma unroll
    for (int i = 0; i < 8; i++)
#pragma unroll
        for (int j = 0; j < 8; j++) acc[i][j] = 0.0f;

    const float* w2e  = w2 + (size_t)e * H_DIM * F_DIM + (size_t)n0 * F_DIM;
    const float* actb = g_act + (size_t)(e * T_TOK + m0) * F_DIM;

    const int lr  = tid >> 2;        // 0..63
    const int lk4 = (tid & 3) * 4;

    for (int k0 = 0; k0 < F_DIM; k0 += 16) {
#pragma unroll
        for (int r = 0; r < 2; r++) {
            int row = lr + r * 64;
            float4 va = *(const float4*)(actb + (size_t)row * F_DIM + k0 + lk4);
            As[(lk4 + 0) * 132 + row] = va.x;
            As[(lk4 + 1) * 132 + row] = va.y;
            As[(lk4 + 2) * 132 + row] = va.z;
            As[(lk4 + 3) * 132 + row] = va.w;
            float4 vb = *(const float4*)(w2e + (size_t)row * F_DIM + k0 + lk4);
            Bs[(lk4 + 0) * 132 + row] = vb.x;
            Bs[(lk4 + 1) * 132 + row] = vb.y;
            Bs[(lk4 + 2) * 132 + row] = vb.z;
            Bs[(lk4 + 3) * 132 + row] = vb.w;
        }
        __syncthreads();

#pragma unroll
        for (int kk = 0; kk < 16; kk++) {
            float4 a0 = *(const float4*)&As[kk * 132 + ty * 8];
            float4 a1 = *(const float4*)&As[kk * 132 + ty * 8 + 4];
            float4 b0 = *(const float4*)&Bs[kk * 132 + tx * 8];
            float4 b1 = *(const float4*)&Bs[kk * 132 + tx * 8 + 4];
            float a[8] = {a0.x, a0.y, a0.z, a0.w, a1.x, a1.y, a1.z, a1.w};
            float b[8] = {b0.x, b0.y, b0.z, b0.w, b1.x, b1.y, b1.z, b1.w};
#pragma unroll
            for (int i = 0; i < 8; i++)
#pragma unroll
                for (int j = 0; j < 8; j++) acc[i][j] += a[i] * b[j];
        }
        __syncthreads();
    }

    // epilogue: out[token] += w * y   (exactly 2 atomic adds per output element
    // across the whole launch -> bitwise-commutative, deterministic)
#pragma unroll
    for (int i = 0; i < 8; i++) {
        int row = ty * 8 + i;
        if (m0 + row < cnt) {
            float  w    = g_wgt[e * T_TOK + m0 + row];
            float* orow = out + (size_t)stok[row] * H_DIM + n0 + tx * 8;
#pragma unroll
            for (int j = 0; j < 8; j++) {
                atomicAdd(&orow[j], w * acc[i][j]);
            }
        }
    }
}

// ---------------------------------------------------------------------------
// Launch
// ---------------------------------------------------------------------------
extern "C" void kernel_launch(void* const* d_in, const int* in_sizes, int n_in,
                              void* d_out, int out_size) {
    (void)in_sizes; (void)n_in; (void)out_size;
    const float* hidden = (const float*)d_in[0];
    const float* logits = (const float*)d_in[1];
    const float* w1     = (const float*)d_in[2];
    const float* w2     = (const float*)d_in[3];
    float*       out    = (float*)d_out;

    init_kernel<<<2048, 256>>>(out);
    route_kernel<<<T_TOK / 256, 256>>>(logits);

    dim3 g1(T_TOK / 128, F_DIM / 64, E_NUM);   // (64, 22, 8)
    gemm1_kernel<<<g1, 256>>>(hidden, w1);

    dim3 g2(T_TOK / 128, H_DIM / 128, E_NUM);  // (64, 16, 8)
    gemm2_kernel<<<g2, 256>>>(w2, out);
}